// round 16
// baseline (speedup 1.0000x reference)
#include <cuda_runtime.h>
#include <math.h>
#include <stdint.h>

#define TT   2048
#define CC   512
#define HH   8
#define DHD  64
#define WINW 48
#define C3   1536
#define QB   32
#define BAND 128

// Scratch (device globals — no allocation allowed)
__device__ float g_qkv[TT * C3];
__device__ float g_y[TT * CC];
__device__ float g_x32[TT * CC];      // tf32-rounded x, 8-chunk pair-interleaved
__device__ float g_wqkv32[CC * C3];   // tf32-rounded W_qkv (plain)
__device__ float g_wout32[CC * CC];   // tf32-rounded W_out (plain)

// ---------------------------------------------------------------------------
__device__ __forceinline__ float to_tf32(float x) {
    float y;
    asm("cvt.rna.tf32.f32 %0, %1;" : "=f"(y) : "f"(x));
    return y;
}

__device__ __forceinline__ void split_tf32(float v, uint32_t& hi, uint32_t& lo) {
    float h = to_tf32(v);
    float l = to_tf32(v - h);
    hi = __float_as_uint(h);
    lo = __float_as_uint(l);
}

__device__ __forceinline__ void mma_tf32(float& c0, float& c1, float& c2, float& c3,
                                         uint32_t a0, uint32_t a1, uint32_t a2, uint32_t a3,
                                         uint32_t b0, uint32_t b1) {
    asm volatile(
        "mma.sync.aligned.m16n8k8.row.col.f32.tf32.tf32.f32 "
        "{%0,%1,%2,%3}, {%4,%5,%6,%7}, {%8,%9}, {%0,%1,%2,%3};"
        : "+f"(c0), "+f"(c1), "+f"(c2), "+f"(c3)
        : "r"(a0), "r"(a1), "r"(a2), "r"(a3), "r"(b0), "r"(b1));
}

#define CP_ASYNC16(dst, src) \
    asm volatile("cp.async.cg.shared.global [%0], [%1], 16;\n" :: "r"(dst), "l"(src))
#define CP_COMMIT() asm volatile("cp.async.commit_group;\n" ::)
#define CP_WAIT2()  asm volatile("cp.async.wait_group 2;\n" ::)
#define CP_WAIT1()  asm volatile("cp.async.wait_group 1;\n" ::)

// ---------------------------------------------------------------------------
// Prep: tf32-round x (pair-interleaved), W_qkv, W_out. (No zero-fill needed —
// gemm2 is non-split plain-store now.)
// ---------------------------------------------------------------------------
#define XCH   (TT * CC / 8)
#define WQF4  (CC * C3 / 4)
#define WOF4  (CC * CC / 4)
#define PREPTH (XCH + WQF4 + WOF4)

__global__ void prep_tf32_kernel(const float4* __restrict__ x,
                                 const float4* __restrict__ wq,
                                 const float4* __restrict__ wo,
                                 float4* __restrict__ xo,
                                 float4* __restrict__ wqo,
                                 float4* __restrict__ woo) {
    int i = blockIdx.x * blockDim.x + threadIdx.x;
    if (i >= PREPTH) return;
    if (i < XCH) {
        const float4 a = x[2 * i];
        const float4 b = x[2 * i + 1];
        float4 o0, o1;
        o0.x = to_tf32(a.x); o0.y = to_tf32(b.x);
        o0.z = to_tf32(a.y); o0.w = to_tf32(b.y);
        o1.x = to_tf32(a.z); o1.y = to_tf32(b.z);
        o1.z = to_tf32(a.w); o1.w = to_tf32(b.w);
        xo[2 * i]     = o0;
        xo[2 * i + 1] = o1;
        return;
    }
    i -= XCH;
    if (i < WQF4) {
        float4 v = wq[i];
        v.x = to_tf32(v.x); v.y = to_tf32(v.y);
        v.z = to_tf32(v.z); v.w = to_tf32(v.w);
        wqo[i] = v;
        return;
    }
    i -= WQF4;
    float4 v = wo[i];
    v.x = to_tf32(v.x); v.y = to_tf32(v.y);
    v.z = to_tf32(v.z); v.w = to_tf32(v.w);
    woo[i] = v;
}

// ---------------------------------------------------------------------------
// GEMM1 (R14, proven): cp.async 4-stage, BK=16, block 128x64, 8 warps,
// pair-interleaved A (LDS.64 fragments). PDL-aware.
// ---------------------------------------------------------------------------
#define GBM 128
#define GBN 64
#define GBK 16
#define NSTAGE 4
#define A_STG1 (128 * 24)
#define B_ST (16 * 72)
#define G1_SMEM_BYTES ((NSTAGE * A_STG1 + NSTAGE * B_ST) * 4)

template<int M, int N, int K>
__global__ void __launch_bounds__(256, 3) gemm1_kernel(
    const float* __restrict__ A,
    const float* __restrict__ B,
    float* __restrict__ Cout)
{
    constexpr int APITCH = 24;

    extern __shared__ float smemf[];
    float* As = smemf;
    float* Bs = smemf + NSTAGE * A_STG1;

    const int t    = threadIdx.x;
    const int lane = t & 31;
    const int w    = t >> 5;
    const int wm   = (w >> 1) * 32;
    const int wn   = (w & 1) * 32;
    const int m0   = blockIdx.y * GBM;
    const int n0   = blockIdx.x * GBN;
    const int lq   = lane >> 2;
    const int lr   = lane & 3;

    const int arow = t >> 1;
    const int ak8  = t & 1;
    const int brow = t >> 4;
    const int bcol = (t & 15) * 4;

    const float* Abase = A + (size_t)(m0 + arow) * K + ak8 * 8;
    const float* Bbase = B + (size_t)brow * N + n0 + bcol;

    uint32_t as_base = (uint32_t)__cvta_generic_to_shared(As) +
                       (arow * APITCH + ak8 * 8) * 4;
    uint32_t bs_base = (uint32_t)__cvta_generic_to_shared(Bs) +
                       (brow * 72 + bcol) * 4;

    float c[2][4][4];
#pragma unroll
    for (int mt = 0; mt < 2; mt++)
#pragma unroll
        for (int nt = 0; nt < 4; nt++)
#pragma unroll
            for (int i = 0; i < 4; i++) c[mt][nt][i] = 0.f;

    const int NSTEP = K / GBK;

    cudaGridDependencySynchronize();

#pragma unroll
    for (int p = 0; p < NSTAGE - 1; p++) {
        const float* asrc = Abase + p * GBK;
        uint32_t adst = as_base + p * A_STG1 * 4;
        CP_ASYNC16(adst, asrc);
        CP_ASYNC16(adst + 16, asrc + 4);
        const float* bsrc = Bbase + (size_t)p * GBK * N;
        CP_ASYNC16(bs_base + p * B_ST * 4, bsrc);
        CP_COMMIT();
    }

    for (int s = 0; s < NSTEP; s++) {
        CP_WAIT2();
        __syncthreads();

        if (s + NSTAGE - 1 < NSTEP) {
            const int stg = (s + NSTAGE - 1) & (NSTAGE - 1);
            const float* asrc = Abase + (s + NSTAGE - 1) * GBK;
            uint32_t adst = as_base + stg * A_STG1 * 4;
            CP_ASYNC16(adst, asrc);
            CP_ASYNC16(adst + 16, asrc + 4);
            const float* bsrc = Bbase + (size_t)(s + NSTAGE - 1) * GBK * N;
            CP_ASYNC16(bs_base + stg * B_ST * 4, bsrc);
        }
        CP_COMMIT();

        const float* AsS = As + (s & (NSTAGE - 1)) * A_STG1;
        const float* BsS = Bs + (s & (NSTAGE - 1)) * B_ST;

#pragma unroll
        for (int kk8 = 0; kk8 < 2; kk8++) {
            const int kb = kk8 * 8;
            uint32_t af[2][4];
#pragma unroll
            for (int mt = 0; mt < 2; mt++) {
                const float2* AsS2 = (const float2*)AsS;
                const int r0 = (wm + mt * 16 + lq) * (APITCH / 2) + kk8 * 4 + lr;
                const float2 p0 = AsS2[r0];
                const float2 p1 = AsS2[r0 + 8 * (APITCH / 2)];
                af[mt][0] = __float_as_uint(p0.x);
                af[mt][1] = __float_as_uint(p1.x);
                af[mt][2] = __float_as_uint(p0.y);
                af[mt][3] = __float_as_uint(p1.y);
            }
            uint32_t bf[4][2];
#pragma unroll
            for (int nt = 0; nt < 4; nt++) {
                const int col = wn + nt * 8 + lq;
                bf[nt][0] = __float_as_uint(BsS[(kb + lr) * 72 + col]);
                bf[nt][1] = __float_as_uint(BsS[(kb + lr + 4) * 72 + col]);
            }
#pragma unroll
            for (int mt = 0; mt < 2; mt++)
#pragma unroll
                for (int nt = 0; nt < 4; nt++)
                    mma_tf32(c[mt][nt][0], c[mt][nt][1], c[mt][nt][2], c[mt][nt][3],
                             af[mt][0], af[mt][1], af[mt][2], af[mt][3],
                             bf[nt][0], bf[nt][1]);
        }
    }

#pragma unroll
    for (int mt = 0; mt < 2; mt++) {
#pragma unroll
        for (int nt = 0; nt < 4; nt++) {
            const int row0 = m0 + wm + mt * 16 + lq;
            const int col  = n0 + wn + nt * 8 + 2 * lr;
            *(float2*)&Cout[(size_t)row0 * N + col] =
                make_float2(c[mt][nt][0], c[mt][nt][1]);
            *(float2*)&Cout[(size_t)(row0 + 8) * N + col] =
                make_float2(c[mt][nt][2], c[mt][nt][3]);
        }
    }
}

// ---------------------------------------------------------------------------
// GEMM2 v2: BK=32 (16 steps instead of 32 — halves per-step fixed cost),
// 3-stage cp.async, block 128x64, plain store (no split-K, no atomics).
// A smem pitch 36 words (bank-bijective: 4*lq+lr), B pitch 72.
// ---------------------------------------------------------------------------
#define G2BK 32
#define G2NS 3
#define A_P2 36
#define A_ST2 (128 * A_P2)          // 4608 floats
#define B_ST2 (G2BK * 72)           // 2304 floats
#define G2_SMEM_BYTES (G2NS * (A_ST2 + B_ST2) * 4)   // 82944

template<int M, int N, int K>
__global__ void __launch_bounds__(256, 2) gemm2_kernel(
    const float* __restrict__ A,
    const float* __restrict__ B,
    float* __restrict__ Cout)
{
    extern __shared__ float smemf[];
    float* As = smemf;
    float* Bs = smemf + G2NS * A_ST2;

    const int t    = threadIdx.x;
    const int lane = t & 31;
    const int w    = t >> 5;
    const int wm   = (w >> 1) * 32;
    const int wn   = (w & 1) * 32;
    const int m0   = blockIdx.y * GBM;
    const int n0   = blockIdx.x * GBN;
    const int lq   = lane >> 2;
    const int lr   = lane & 3;

    // A staging: thread -> row t>>1, 16-float half (t&1), 4 cp.async of 16B
    const int arow = t >> 1;
    const int ak16 = (t & 1) * 16;
    // B staging: thread -> row t>>3 (0..31), col (t&7)*8, 2 cp.async
    const int brow = t >> 3;
    const int bcol = (t & 7) * 8;

    const float* Abase = A + (size_t)(m0 + arow) * K + ak16;
    const float* Bbase = B + (size_t)brow * N + n0 + bcol;

    uint32_t as_base = (uint32_t)__cvta_generic_to_shared(As) +
                       (arow * A_P2 + ak16) * 4;
    uint32_t bs_base = (uint32_t)__cvta_generic_to_shared(Bs) +
                       (brow * 72 + bcol) * 4;

    float c[2][4][4];
#pragma unroll
    for (int mt = 0; mt < 2; mt++)
#pragma unroll
        for (int nt = 0; nt < 4; nt++)
#pragma unroll
            for (int i = 0; i < 4; i++) c[mt][nt][i] = 0.f;

    const int NSTEP = K / G2BK;     // 16

    cudaGridDependencySynchronize();

    // prologue: stages 0, 1
#pragma unroll
    for (int p = 0; p < G2NS - 1; p++) {
        const float* asrc = Abase + p * G2BK;
        uint32_t adst = as_base + p * A_ST2 * 4;
        CP_ASYNC16(adst,      asrc);
        CP_ASYNC16(adst + 16, asrc + 4);
        CP_ASYNC16(adst + 32, asrc + 8);
        CP_ASYNC16(adst + 48, asrc + 12);
        const float* bsrc = Bbase + (size_t)p * G2BK * N;
        uint32_t bdst = bs_base + p * B_ST2 * 4;
        CP_ASYNC16(bdst,      bsrc);
        CP_ASYNC16(bdst + 16, bsrc + 4);
        CP_COMMIT();
    }

    for (int s = 0; s < NSTEP; s++) {
        CP_WAIT1();
        __syncthreads();

        if (s + G2NS - 1 < NSTEP) {
            const int stg = (s + G2NS - 1) % G2NS;
            const float* asrc = Abase + (s + G2NS - 1) * G2BK;
            uint32_t adst = as_base + stg * A_ST2 * 4;
            CP_ASYNC16(adst,      asrc);
            CP_ASYNC16(adst + 16, asrc + 4);
            CP_ASYNC16(adst + 32, asrc + 8);
            CP_ASYNC16(adst + 48, asrc + 12);
            const float* bsrc = Bbase + (size_t)(s + G2NS - 1) * G2BK * N;
            uint32_t bdst = bs_base + stg * B_ST2 * 4;
            CP_ASYNC16(bdst,      bsrc);
            CP_ASYNC16(bdst + 16, bsrc + 4);
        }
        CP_COMMIT();

        const float* AsS = As + (s % G2NS) * A_ST2;
        const float* BsS = Bs + (s % G2NS) * B_ST2;

#pragma unroll
        for (int kk8 = 0; kk8 < 4; kk8++) {
            const int kb = kk8 * 8;
            uint32_t af[2][4];
#pragma unroll
            for (int mt = 0; mt < 2; mt++) {
                const int r0 = (wm + mt * 16 + lq) * A_P2;
                af[mt][0] = __float_as_uint(AsS[r0 + kb + lr]);
                af[mt][1] = __float_as_uint(AsS[r0 + 8 * A_P2 + kb + lr]);
                af[mt][2] = __float_as_uint(AsS[r0 + kb + lr + 4]);
                af[mt][3] = __float_as_uint(AsS[r0 + 8 * A_P2 + kb + lr + 4]);
            }
            uint32_t bf[4][2];
#pragma unroll
            for (int nt = 0; nt < 4; nt++) {
                const int col = wn + nt * 8 + lq;
                bf[nt][0] = __float_as_uint(BsS[(kb + lr) * 72 + col]);
                bf[nt][1] = __float_as_uint(BsS[(kb + lr + 4) * 72 + col]);
            }
#pragma unroll
            for (int mt = 0; mt < 2; mt++)
#pragma unroll
                for (int nt = 0; nt < 4; nt++)
                    mma_tf32(c[mt][nt][0], c[mt][nt][1], c[mt][nt][2], c[mt][nt][3],
                             af[mt][0], af[mt][1], af[mt][2], af[mt][3],
                             bf[nt][0], bf[nt][1]);
        }
    }

#pragma unroll
    for (int mt = 0; mt < 2; mt++) {
#pragma unroll
        for (int nt = 0; nt < 4; nt++) {
            const int row0 = m0 + wm + mt * 16 + lq;
            const int col  = n0 + wn + nt * 8 + 2 * lr;
            *(float2*)&Cout[(size_t)row0 * N + col] =
                make_float2(c[mt][nt][0], c[mt][nt][1]);
            *(float2*)&Cout[(size_t)(row0 + 8) * N + col] =
                make_float2(c[mt][nt][2], c[mt][nt][3]);
        }
    }
}

// ---------------------------------------------------------------------------
// Attention v7 (R13/R14 best): attn5 phases, K/V unsplit fp32 in smem, hi/lo
// B-splits in-register, 3 CTAs/SM. PDL-aware.
// ---------------------------------------------------------------------------
#define AST 68
#define BST 132
#define OFF_QH 0
#define OFF_QL 2176
#define OFF_KF 4352
#define OFF_S  13056
#define OFF_WH OFF_QH
#define OFF_WL OFF_S
#define OFF_VF OFF_KF
#define OFF_IDX 17280
#define ATTN_SMEM_FLOATS (OFF_IDX + BAND + QB)
#define ATTN_SMEM_BYTES  (ATTN_SMEM_FLOATS * 4)

__global__ void __launch_bounds__(256, 3) attn7_kernel(
    const float* __restrict__ qkv,
    const int* __restrict__ perms,
    float* __restrict__ y)
{
    extern __shared__ float sm[];
    int* nb  = (int*)(sm + OFF_IDX);
    int* pts = nb + BAND;

    const int h    = blockIdx.y;
    const int t0   = blockIdx.x * QB;
    const int t    = threadIdx.x;
    const int lane = t & 31;
    const int w    = t >> 5;
    const int lq   = lane >> 2;
    const int lr   = lane & 3;

    const int* __restrict__ perm = perms + h * TT;

    for (int i = t; i < BAND + QB; i += 256) {
        if (i < BAND) {
            int j  = t0 - WINW + i;
            int jc = min(max(j, 0), TT - 1);
            nb[i] = perm[jc];
        } else {
            pts[i - BAND] = perm[t0 + (i - BAND)];
        }
    }
    __syncthreads();

    cudaGridDependencySynchronize();

    {
        const int row = t >> 3;
        const int d0  = (t & 7) * 8;
        const float* src = qkv + (size_t)pts[row] * C3 + h * DHD + d0;
        float4 v0 = *(const float4*)src;
        float4 v1 = *(const float4*)(src + 4);
        float vv[8] = {v0.x, v0.y, v0.z, v0.w, v1.x, v1.y, v1.z, v1.w};
        float hi[8], lo[8];
#pragma unroll
        for (int i = 0; i < 8; i++) {
            float s = vv[i] * 0.125f;
            hi[i] = to_tf32(s);
            lo[i] = to_tf32(s - hi[i]);
        }
        const int o = row * AST + d0;
        *(float4*)&sm[OFF_QH + o]     = make_float4(hi[0], hi[1], hi[2], hi[3]);
        *(float4*)&sm[OFF_QH + o + 4] = make_float4(hi[4], hi[5], hi[6], hi[7]);
        *(float4*)&sm[OFF_QL + o]     = make_float4(lo[0], lo[1], lo[2], lo[3]);
        *(float4*)&sm[OFF_QL + o + 4] = make_float4(lo[4], lo[5], lo[6], lo[7]);
    }
#pragma unroll
    for (int it = 0; it < 4; it++) {
        const int r  = it * 32 + (t >> 3);
        const int d0 = (t & 7) * 8;
        const float* src = qkv + (size_t)nb[r] * C3 + CC + h * DHD + d0;
        float4 v0 = *(const float4*)src;
        float4 v1 = *(const float4*)(src + 4);
        *(float4*)&sm[OFF_KF + r * AST + d0]     = v0;
        *(float4*)&sm[OFF_KF + r * AST + d0 + 4] = v1;
    }

    float2 vr[16];
#pragma unroll
    for (int it = 0; it < 16; it++) {
        const int r = it * 8 + w;
        vr[it] = *(const float2*)&qkv[(size_t)nb[r] * C3 + 2 * CC + h * DHD + 2 * lane];
    }
    __syncthreads();

    {
        float c[2][2][4];
#pragma unroll
        for (int mt = 0; mt < 2; mt++)
#pragma unroll
            for (int nt = 0; nt < 2; nt++)
#pragma unroll
                for (int i = 0; i < 4; i++) c[mt][nt][i] = 0.f;

#pragma unroll
        for (int kb = 0; kb < DHD; kb += 8) {
            uint32_t ah[2][4], al[2][4];
#pragma unroll
            for (int mt = 0; mt < 2; mt++) {
                const int r0 = (mt * 16 + lq) * AST + kb;
                ah[mt][0] = __float_as_uint(sm[OFF_QH + r0 + lr]);
                ah[mt][1] = __float_as_uint(sm[OFF_QH + r0 + 8 * AST + lr]);
                ah[mt][2] = __float_as_uint(sm[OFF_QH + r0 + lr + 4]);
                ah[mt][3] = __float_as_uint(sm[OFF_QH + r0 + 8 * AST + lr + 4]);
                al[mt][0] = __float_as_uint(sm[OFF_QL + r0 + lr]);
                al[mt][1] = __float_as_uint(sm[OFF_QL + r0 + 8 * AST + lr]);
                al[mt][2] = __float_as_uint(sm[OFF_QL + r0 + lr + 4]);
                al[mt][3] = __float_as_uint(sm[OFF_QL + r0 + 8 * AST + lr + 4]);
            }
            uint32_t bh[2][2], bl[2][2];
#pragma unroll
            for (int nt = 0; nt < 2; nt++) {
                const int co = (w * 16 + nt * 8 + lq) * AST + kb;
                split_tf32(sm[OFF_KF + co + lr],     bh[nt][0], bl[nt][0]);
                split_tf32(sm[OFF_KF + co + lr + 4], bh[nt][1], bl[nt][1]);
            }
#pragma unroll
            for (int mt = 0; mt < 2; mt++)
#pragma unroll
                for (int nt = 0; nt < 2; nt++) {
                    mma_tf32(c[mt][nt][0], c[mt][nt][1], c[mt][nt][2], c[mt][nt][3],
                             ah[mt][0], ah[mt][1], ah[mt][2], ah[mt][3],
                             bh[nt][0], bh[nt][1]);
                    mma_tf32(c[mt][nt][0], c[mt][nt][1], c[mt][nt][2], c[mt][nt][3],
                             ah[mt][0], ah[mt][1], ah[mt][2], ah[mt][3],
                             bl[nt][0], bl[nt][1]);
                    mma_tf32(c[mt][nt][0], c[mt][nt][1], c[mt][nt][2], c[mt][nt][3],
                             al[mt][0], al[mt][1], al[mt][2], al[mt][3],
                             bh[nt][0], bh[nt][1]);
                }
        }
#pragma unroll
        for (int mt = 0; mt < 2; mt++)
#pragma unroll
            for (int nt = 0; nt < 2; nt++) {
                const int q0  = mt * 16 + lq;
                const int col = w * 16 + nt * 8 + 2 * lr;
                *(float2*)&sm[OFF_S + q0 * BST + col] =
                    make_float2(c[mt][nt][0], c[mt][nt][1]);
                *(float2*)&sm[OFF_S + (q0 + 8) * BST + col] =
                    make_float2(c[mt][nt][2], c[mt][nt][3]);
            }
    }
    __syncthreads();

#pragma unroll
    for (int it = 0; it < 16; it++) {
        const int r = it * 8 + w;
        *(float2*)&sm[OFF_VF + r * AST + 2 * lane] = vr[it];
    }

    for (int qq = w; qq < QB; qq += 8) {
        const int pt = pts[qq];
        float v[4];
#pragma unroll
        for (int cc = 0; cc < 4; cc++) {
            const int r = lane + 32 * cc;
            const bool m = (r >= qq) && (r <= qq + 96) &&
                           ((unsigned)(t0 - WINW + r) < (unsigned)TT) &&
                           (nb[r] <= pt);
            v[cc] = m ? sm[OFF_S + qq * BST + r] : -INFINITY;
        }
        float mx = fmaxf(fmaxf(v[0], v[1]), fmaxf(v[2], v[3]));
#pragma unroll
        for (int off = 16; off; off >>= 1)
            mx = fmaxf(mx, __shfl_xor_sync(0xffffffffu, mx, off));
        float e[4], s = 0.f;
#pragma unroll
        for (int cc = 0; cc < 4; cc++) { e[cc] = __expf(v[cc] - mx); s += e[cc]; }
#pragma unroll
        for (int off = 16; off; off >>= 1)
            s += __shfl_xor_sync(0xffffffffu, s, off);
        const float inv = 1.f / s;
#pragma unroll
        for (int cc = 0; cc < 4; cc++) {
            const int r = lane + 32 * cc;
            const float wv = e[cc] * inv;
            const float hi = to_tf32(wv);
            sm[OFF_WH + qq * BST + r] = hi;
            sm[OFF_WL + qq * BST + r] = to_tf32(wv - hi);
        }
    }
    __syncthreads();

    {
        const int wm = (w & 1) * 16;
        const int ng = (w >> 1) * 16;
        float c[2][4];
#pragma unroll
        for (int nt = 0; nt < 2; nt++)
#pragma unroll
            for (int i = 0; i < 4; i++) c[nt][i] = 0.f;

#pragma unroll
        for (int kb = 0; kb < BAND; kb += 8) {
            uint32_t ah[4], al[4];
            const int r0 = (wm + lq) * BST + kb;
            ah[0] = __float_as_uint(sm[OFF_WH + r0 + lr]);
            ah[1] = __float_as_uint(sm[OFF_WH + r0 + 8 * BST + lr]);
            ah[2] = __float_as_uint(sm[OFF_WH + r0 + lr + 4]);
            ah[3] = __float_as_uint(sm[OFF_WH + r0 + 8 * BST + lr + 4]);
            al[0] = __float_as_uint(sm[OFF_WL + r0 + lr]);
            al[1] = __float_as_uint(sm[OFF_WL + r0 + 8 * BST + lr]);
            al[2] = __float_as_uint(sm[OFF_WL + r0 + lr + 4]);
            al[3] = __float_as_uint(sm[OFF_WL + r0 + 8 * BST + lr + 4]);
            uint32_t bh[2][2], bl[2][2];
#pragma unroll
            for (int nt = 0; nt < 2; nt++) {
                const int col = ng + nt * 8 + lq;
                split_tf32(sm[OFF_VF + (kb + lr) * AST + col],     bh[nt][0], bl[nt][0]);
                split_tf32(sm[OFF_VF + (kb + lr + 4) * AST + col], bh[nt][1], bl[nt][1]);
            }
#pragma unroll
            for (int nt = 0; nt < 2; nt++) {
                mma_tf32(c[nt][0], c[nt][1], c[nt][2], c[nt][3],
                         ah[0], ah[1], ah[2], ah[3], bh[nt][0], bh[nt][1]);
                mma_tf32(c[nt][0], c[nt][1], c[nt][2], c[nt][3],
                         ah[0], ah[1], ah[2], ah[3], bl[nt][0], bl[nt][1]);
                mma_tf32(c[nt][0], c[nt][1], c[nt][2], c[nt][3],
                         al[0], al[1], al[2], al[3], bh[nt][0], bh[nt][1]);
            }
        }

#pragma unroll
        for (int nt = 0; nt < 2; nt++) {
            const int d  = ng + nt * 8 + 2 * lr;
            const int q0 = wm + lq;
            *(float2*)&y[(size_t)pts[q0] * CC + h * DHD + d] =
                make_float2(to_tf32(c[nt][0]), to_tf32(c[nt][1]));
            *(float2*)&y[(size_t)pts[q0 + 8] * CC + h * DHD + d] =
                make_float2(to_tf32(c[nt][2]), to_tf32(c[nt][3]));
        }
    }
}

// ---------------------------------------------------------------------------
extern "C" void kernel_launch(void* const* d_in, const int* in_sizes, int n_in,
                              void* d_out, int out_size) {
    (void)in_sizes; (void)n_in; (void)out_size;
    const float* x     = (const float*)d_in[0];
    const float* Wqkv  = (const float*)d_in[1];
    const float* Wout  = (const float*)d_in[2];
    const int*   perms = (const int*)d_in[3];
    float*       out   = (float*)d_out;

    float *qkv, *y, *x32, *wq32, *wo32;
    cudaGetSymbolAddress((void**)&qkv,  g_qkv);
    cudaGetSymbolAddress((void**)&y,    g_y);
    cudaGetSymbolAddress((void**)&x32,  g_x32);
    cudaGetSymbolAddress((void**)&wq32, g_wqkv32);
    cudaGetSymbolAddress((void**)&wo32, g_wout32);

    cudaFuncSetAttribute((const void*)gemm1_kernel<TT, C3, CC>,
                         cudaFuncAttributeMaxDynamicSharedMemorySize, G1_SMEM_BYTES);
    cudaFuncSetAttribute((const void*)gemm2_kernel<TT, CC, CC>,
                         cudaFuncAttributeMaxDynamicSharedMemorySize, G2_SMEM_BYTES);
    cudaFuncSetAttribute(attn7_kernel,
                         cudaFuncAttributeMaxDynamicSharedMemorySize, ATTN_SMEM_BYTES);

    cudaLaunchAttribute pdl_attr;
    pdl_attr.id = cudaLaunchAttributeProgrammaticStreamSerialization;
    pdl_attr.val.programmaticStreamSerializationAllowed = 1;

    // 0) tf32-round + interleave x, round weights
    prep_tf32_kernel<<<(PREPTH + 255) / 256, 256>>>(
        (const float4*)x, (const float4*)Wqkv, (const float4*)Wout,
        (float4*)x32, (float4*)wq32, (float4*)wo32);

    // 1) qkv = x32 @ wq32 (PDL over prep)
    {
        cudaLaunchConfig_t cfg = {};
        cfg.gridDim = dim3(C3 / GBN, TT / GBM, 1);
        cfg.blockDim = dim3(256, 1, 1);
        cfg.dynamicSmemBytes = G1_SMEM_BYTES;
        cfg.stream = 0;
        cfg.attrs = &pdl_attr;
        cfg.numAttrs = 1;
        cudaLaunchKernelEx(&cfg, gemm1_kernel<TT, C3, CC>,
                           (const float*)x32, (const float*)wq32, qkv);
    }
    // 2) attention (PDL over gemm1)
    {
        cudaLaunchConfig_t cfg = {};
        cfg.gridDim = dim3(TT / QB, HH, 1);
        cfg.blockDim = dim3(256, 1, 1);
        cfg.dynamicSmemBytes = ATTN_SMEM_BYTES;
        cfg.stream = 0;
        cfg.attrs = &pdl_attr;
        cfg.numAttrs = 1;
        cudaLaunchKernelEx(&cfg, attn7_kernel,
                           (const float*)qkv, (const int*)perms, y);
    }
    // 3) out = y @ wo32 (BK=32, non-split, PDL over attention)
    {
        cudaLaunchConfig_t cfg = {};
        cfg.gridDim = dim3(CC / GBN, TT / GBM, 1);
        cfg.blockDim = dim3(256, 1, 1);
        cfg.dynamicSmemBytes = G2_SMEM_BYTES;
        cfg.stream = 0;
        cfg.attrs = &pdl_attr;
        cfg.numAttrs = 1;
        cudaLaunchKernelEx(&cfg, gemm2_kernel<TT, CC, CC>,
                           (const float*)y, (const float*)wo32, out);
    }
}